// round 1
// baseline (speedup 1.0000x reference)
#include <cuda_runtime.h>

namespace {
constexpr int T_STEPS = 1000;
constexpr int B       = 256;
constexpr int IN_DIM  = 3;
constexpr int H       = 512;
constexpr int OUT_DIM = 2;
constexpr int HPT     = 4;            // neurons (h) per thread
constexpr int NT      = H / HPT;      // 128 threads per block
constexpr int TAIL    = 10;           // readout window
}

__global__ __launch_bounds__(NT)
void snn_fused_kernel(const float* __restrict__ x,
                      const float* __restrict__ W1,
                      const float* __restrict__ W2,
                      float* __restrict__ out,
                      long long avg_off)
{
    __shared__ float4 xs[T_STEPS];          // 16 KB: per-b input, padded to float4
    __shared__ float  redbuf[2][NT / 32];

    const int b   = blockIdx.x;
    const int tid = threadIdx.x;

    // Stage this batch element's whole input sequence into smem (3 MB total
    // across grid, L2-resident after warmup; independent loads -> MLP hides lat).
    for (int t = tid; t < T_STEPS; t += NT) {
        const float* xp = x + ((size_t)t * B + b) * IN_DIM;
        xs[t] = make_float4(xp[0], xp[1], xp[2], 0.0f);
    }

    // Per-thread weights for its 4 neurons
    const int h0 = tid * HPT;
    float w10[HPT], w11[HPT], w12[HPT];
#pragma unroll
    for (int j = 0; j < HPT; ++j) {
        const float* wp = W1 + (size_t)(h0 + j) * IN_DIM;
        w10[j] = wp[0]; w11[j] = wp[1]; w12[j] = wp[2];
    }
    const float4 w2r0 = *reinterpret_cast<const float4*>(W2 + h0);       // W2[0, h0..h0+3]
    const float4 w2r1 = *reinterpret_cast<const float4*>(W2 + H + h0);   // W2[1, h0..h0+3]

    __syncthreads();

    float mem[HPT];
#pragma unroll
    for (int j = 0; j < HPT; ++j) mem[j] = 0.0f;

    float* outp = out + (size_t)b * H + h0;

    // ---- main recurrence (no readout) ----
#pragma unroll 2
    for (int t = 0; t < T_STEPS - TAIL; ++t) {
        const float4 xv = xs[t];
        float s[HPT];
#pragma unroll
        for (int j = 0; j < HPT; ++j) {
            // cur = x0*w0 (+fma) x1*w1 (+fma) x2*w2  -- cublas-like k-ascending fma chain
            float cur = __fmaf_rn(xv.z, w12[j],
                        __fmaf_rn(xv.y, w11[j],
                        __fmul_rn(xv.x, w10[j])));
            // reset from PREVIOUS mem; mem_new = (0.8*mem + cur) * (1 - reset)
            float vm = __fadd_rn(__fmul_rn(0.8f, mem[j]), cur);
            float mn = (mem[j] > 1.0f) ? 0.0f : vm;
            mem[j] = mn;
            s[j] = (mn > 1.0f) ? 1.0f : 0.0f;   // == (mem_new - 1 > 0) exactly in fp32
        }
        float4 spk; spk.x = s[0]; spk.y = s[1]; spk.z = s[2]; spk.w = s[3];
        *reinterpret_cast<float4*>(outp) = spk;
        outp += B * H;
    }

    // ---- last 10 steps: recurrence + fused sigmoid readout ----
    float acc0 = 0.0f, acc1 = 0.0f;
    const int lane = tid & 31;
    const int warp = tid >> 5;
    for (int t = T_STEPS - TAIL; t < T_STEPS; ++t) {
        const float4 xv = xs[t];
        float s[HPT];
#pragma unroll
        for (int j = 0; j < HPT; ++j) {
            float cur = __fmaf_rn(xv.z, w12[j],
                        __fmaf_rn(xv.y, w11[j],
                        __fmul_rn(xv.x, w10[j])));
            float vm = __fadd_rn(__fmul_rn(0.8f, mem[j]), cur);
            float mn = (mem[j] > 1.0f) ? 0.0f : vm;
            mem[j] = mn;
            s[j] = (mn > 1.0f) ? 1.0f : 0.0f;
        }
        float4 spk; spk.x = s[0]; spk.y = s[1]; spk.z = s[2]; spk.w = s[3];
        *reinterpret_cast<float4*>(outp) = spk;
        outp += B * H;

        // partial dot with W2 rows over this thread's 4 neurons
        float p0 = s[0] * w2r0.x + s[1] * w2r0.y + s[2] * w2r0.z + s[3] * w2r0.w;
        float p1 = s[0] * w2r1.x + s[1] * w2r1.y + s[2] * w2r1.z + s[3] * w2r1.w;
#pragma unroll
        for (int off = 16; off > 0; off >>= 1) {
            p0 += __shfl_down_sync(0xffffffffu, p0, off);
            p1 += __shfl_down_sync(0xffffffffu, p1, off);
        }
        if (lane == 0) { redbuf[0][warp] = p0; redbuf[1][warp] = p1; }
        __syncthreads();
        if (tid == 0) {
            float d0 = redbuf[0][0] + redbuf[0][1] + redbuf[0][2] + redbuf[0][3];
            float d1 = redbuf[1][0] + redbuf[1][1] + redbuf[1][2] + redbuf[1][3];
            acc0 += 1.0f / (1.0f + expf(-d0));
            acc1 += 1.0f / (1.0f + expf(-d1));
        }
        __syncthreads();
    }

    if (tid == 0) {
        float* ao = out + avg_off + (size_t)b * OUT_DIM;
        ao[0] = acc0 * 0.1f;
        ao[1] = acc1 * 0.1f;
    }
}

extern "C" void kernel_launch(void* const* d_in, const int* in_sizes, int n_in,
                              void* d_out, int out_size) {
    const float* x  = (const float*)d_in[0];   // x_seq [1000, 256, 3]
    const float* W1 = (const float*)d_in[1];   // [512, 3]
    const float* W2 = (const float*)d_in[2];   // [2, 512]
    float* out = (float*)d_out;
    // avg_out sits at the end of the concatenated output buffer
    long long avg_off = (long long)out_size - (long long)(B * OUT_DIM);
    snn_fused_kernel<<<B, NT>>>(x, W1, W2, out, avg_off);
}

// round 2
// speedup vs baseline: 1.0221x; 1.0221x over previous
#include <cuda_runtime.h>

namespace {
constexpr int T_STEPS = 1000;
constexpr int B       = 256;
constexpr int IN_DIM  = 3;
constexpr int H       = 512;
constexpr int OUT_DIM = 2;
constexpr int NT      = 512;          // one thread per neuron
constexpr int NWARP   = NT / 32;      // 16
constexpr int TAIL    = 10;           // readout window
}

__global__ __launch_bounds__(NT)
void snn_fused_kernel(const float* __restrict__ x,
                      const float* __restrict__ W1,
                      const float* __restrict__ W2,
                      float* __restrict__ out,
                      long long avg_off)
{
    __shared__ float4 xs[T_STEPS];          // 16 KB: this batch element's inputs, padded
    __shared__ float  redbuf[2][NWARP];

    const int b   = blockIdx.x;
    const int tid = threadIdx.x;

    // Stage the whole input sequence for this b into smem (2 iters/thread).
    for (int t = tid; t < T_STEPS; t += NT) {
        const float* xp = x + ((size_t)t * B + b) * IN_DIM;
        xs[t] = make_float4(xp[0], xp[1], xp[2], 0.0f);
    }

    // This thread's neuron weights
    const int h = tid;
    const float w10 = W1[(size_t)h * IN_DIM + 0];
    const float w11 = W1[(size_t)h * IN_DIM + 1];
    const float w12 = W1[(size_t)h * IN_DIM + 2];
    const float w2r0 = W2[h];        // W2[0, h]
    const float w2r1 = W2[H + h];    // W2[1, h]

    __syncthreads();

    float mem = 0.0f;
    float* outp = out + (size_t)b * H + h;

    // ---- main recurrence (no readout) ----
#pragma unroll 4
    for (int t = 0; t < T_STEPS - TAIL; ++t) {
        const float4 xv = xs[t];
        // cur = x0*w0 (+fma) x1*w1 (+fma) x2*w2  (cublas-like k-ascending chain)
        float cur = __fmaf_rn(xv.z, w12,
                    __fmaf_rn(xv.y, w11,
                    __fmul_rn(xv.x, w10)));
        // reset from PREVIOUS mem; mem_new = (0.8*mem + cur) * (1 - reset)
        float vm = __fadd_rn(__fmul_rn(0.8f, mem), cur);
        float mn = (mem > 1.0f) ? 0.0f : vm;
        mem = mn;
        float s = (mn > 1.0f) ? 1.0f : 0.0f;   // == (mem_new - 1 > 0) exactly in fp32
        *outp = s;
        outp += B * H;
    }

    // ---- last 10 steps: recurrence + fused sigmoid readout ----
    float acc0 = 0.0f, acc1 = 0.0f;
    const int lane = tid & 31;
    const int warp = tid >> 5;
    for (int t = T_STEPS - TAIL; t < T_STEPS; ++t) {
        const float4 xv = xs[t];
        float cur = __fmaf_rn(xv.z, w12,
                    __fmaf_rn(xv.y, w11,
                    __fmul_rn(xv.x, w10)));
        float vm = __fadd_rn(__fmul_rn(0.8f, mem), cur);
        float mn = (mem > 1.0f) ? 0.0f : vm;
        mem = mn;
        float s = (mn > 1.0f) ? 1.0f : 0.0f;
        *outp = s;
        outp += B * H;

        // partial dot with W2 rows (this thread's single neuron)
        float p0 = s * w2r0;
        float p1 = s * w2r1;
#pragma unroll
        for (int off = 16; off > 0; off >>= 1) {
            p0 += __shfl_down_sync(0xffffffffu, p0, off);
            p1 += __shfl_down_sync(0xffffffffu, p1, off);
        }
        if (lane == 0) { redbuf[0][warp] = p0; redbuf[1][warp] = p1; }
        __syncthreads();
        if (tid == 0) {
            float d0 = 0.0f, d1 = 0.0f;
#pragma unroll
            for (int w = 0; w < NWARP; ++w) { d0 += redbuf[0][w]; d1 += redbuf[1][w]; }
            acc0 += 1.0f / (1.0f + expf(-d0));
            acc1 += 1.0f / (1.0f + expf(-d1));
        }
        __syncthreads();
    }

    if (tid == 0) {
        float* ao = out + avg_off + (size_t)b * OUT_DIM;
        ao[0] = acc0 * 0.1f;
        ao[1] = acc1 * 0.1f;
    }
}

extern "C" void kernel_launch(void* const* d_in, const int* in_sizes, int n_in,
                              void* d_out, int out_size) {
    const float* x  = (const float*)d_in[0];   // x_seq [1000, 256, 3]
    const float* W1 = (const float*)d_in[1];   // [512, 3]
    const float* W2 = (const float*)d_in[2];   // [2, 512]
    float* out = (float*)d_out;
    // avg_out sits at the end of the concatenated output buffer
    long long avg_off = (long long)out_size - (long long)(B * OUT_DIM);
    snn_fused_kernel<<<B, NT>>>(x, W1, W2, out, avg_off);
}